// round 2
// baseline (speedup 1.0000x reference)
#include <cuda_runtime.h>
#include <cuda_bf16.h>

#define N_NODES 50000
#define N_EDGES 800000
#define HID 256
#define NG 128

// ---- scratch (static device globals; no allocation) ----
__device__ float g_dinv[N_NODES];
__device__ float g_px[N_NODES * 2];
__device__ float g_aggx[N_NODES * 2];
__device__ float g_h[(size_t)N_NODES * HID];
__device__ float g_p[(size_t)N_NODES * HID];
__device__ float g_agg[(size_t)N_NODES * HID];
__device__ float g_pool[NG * HID];
__device__ float g_cnt[NG];

// ---- degree / norm ----
__global__ void k_init_deg() {
    int i = blockIdx.x * blockDim.x + threadIdx.x;
    if (i < N_NODES) g_dinv[i] = 1.0f;  // self-loop
}

__global__ void k_deg(const int* __restrict__ ei) {
    int e = blockIdx.x * blockDim.x + threadIdx.x;
    if (e < N_EDGES) atomicAdd(&g_dinv[ei[N_EDGES + e]], 1.0f);
}

__global__ void k_rsqrt() {
    int i = blockIdx.x * blockDim.x + threadIdx.x;
    if (i < N_NODES) g_dinv[i] = rsqrtf(g_dinv[i]);
}

// ---- layer 1: aggregate x (2-wide) BEFORE the 2->256 matmul ----
__global__ void k_prep_x(const float* __restrict__ x) {
    int i = blockIdx.x * blockDim.x + threadIdx.x;
    if (i < N_NODES) {
        float d = g_dinv[i];
        float a = d * x[2 * i];
        float b = d * x[2 * i + 1];
        g_px[2 * i] = a;  g_px[2 * i + 1] = b;
        g_aggx[2 * i] = a; g_aggx[2 * i + 1] = b;  // init with self-loop term
    }
}

__global__ void k_scat2(const int* __restrict__ ei) {
    int e = blockIdx.x * blockDim.x + threadIdx.x;
    if (e < N_EDGES) {
        int s = ei[e];
        int d = ei[N_EDGES + e];
        atomicAdd(&g_aggx[2 * d],     g_px[2 * s]);
        atomicAdd(&g_aggx[2 * d + 1], g_px[2 * s + 1]);
    }
}

// h1[i][j] = dinv[i]*(aggx[i]·W1[:,j]) + b1[j]
__global__ void k_layer1(const float* __restrict__ W1, const float* __restrict__ b1) {
    int i = blockIdx.x;
    int j = threadIdx.x;
    float d = g_dinv[i];
    float a0 = g_aggx[2 * i] * d;
    float a1 = g_aggx[2 * i + 1] * d;
    g_h[(size_t)i * HID + j] = a0 * W1[j] + a1 * W1[HID + j] + b1[j];
}

// ---- layers 2..4: prep (relu * dinv, init agg with self term) ----
__global__ void k_prep() {
    int idx = blockIdx.x * blockDim.x + threadIdx.x;  // over N*HID/4
    if (idx < N_NODES * HID / 4) {
        int i = idx >> 6;  // idx*4 / 256
        float4 v = ((const float4*)g_h)[idx];
        float d = g_dinv[i];
        v.x = fmaxf(v.x, 0.f) * d;
        v.y = fmaxf(v.y, 0.f) * d;
        v.z = fmaxf(v.z, 0.f) * d;
        v.w = fmaxf(v.w, 0.f) * d;
        ((float4*)g_p)[idx] = v;
        ((float4*)g_agg)[idx] = v;
    }
}

// one warp per edge: agg[dst] += p[src], 8 floats/lane
__global__ void k_scat(const int* __restrict__ ei) {
    int w = (blockIdx.x * blockDim.x + threadIdx.x) >> 5;
    int l = threadIdx.x & 31;
    if (w < N_EDGES) {
        int s = ei[w];
        int d = ei[N_EDGES + w];
        const float* ps = g_p + (size_t)s * HID;
        float* ad = g_agg + (size_t)d * HID;
#pragma unroll
        for (int i = 0; i < 8; i++) {
            int o = l + i * 32;
            atomicAdd(ad + o, __ldg(ps + o));
        }
    }
}

// ---- SGEMM: h = (dinv ⊙ agg) @ W + bias  (dinv folded into epilogue) ----
// BM=64 BN=64 BK=32, 256 threads (16x16), 4x4 microtile
__global__ void k_gemm(const float* __restrict__ W, const float* __restrict__ bias) {
    __shared__ float As[32][65];  // transposed A tile, padded
    __shared__ float Ws[32][64];
    int tx = threadIdx.x & 15;
    int ty = threadIdx.x >> 4;
    int rowBase = blockIdx.y * 64;
    int colBase = blockIdx.x * 64;
    float acc[4][4] = {};

    for (int k0 = 0; k0 < HID; k0 += 32) {
#pragma unroll
        for (int i = 0; i < 8; i++) {
            int li = threadIdx.x + i * 256;
            int r = li >> 5, kk = li & 31;
            int gr = rowBase + r;
            As[kk][r] = (gr < N_NODES) ? g_agg[(size_t)gr * HID + k0 + kk] : 0.f;
        }
#pragma unroll
        for (int i = 0; i < 8; i++) {
            int li = threadIdx.x + i * 256;
            int kk = li >> 6, c = li & 63;
            Ws[kk][c] = W[(size_t)(k0 + kk) * HID + colBase + c];
        }
        __syncthreads();
#pragma unroll
        for (int k = 0; k < 32; k++) {
            float a[4], b[4];
#pragma unroll
            for (int j = 0; j < 4; j++) { a[j] = As[k][ty * 4 + j]; b[j] = Ws[k][tx * 4 + j]; }
#pragma unroll
            for (int j = 0; j < 4; j++)
#pragma unroll
                for (int i = 0; i < 4; i++) acc[j][i] += a[j] * b[i];
        }
        __syncthreads();
    }

#pragma unroll
    for (int j = 0; j < 4; j++) {
        int r = rowBase + ty * 4 + j;
        if (r < N_NODES) {
            float d = g_dinv[r];
#pragma unroll
            for (int i = 0; i < 4; i++) {
                int c = colBase + tx * 4 + i;
                g_h[(size_t)r * HID + c] = d * acc[j][i] + bias[c];
            }
        }
    }
}

// ---- pooling ----
__global__ void k_pool_zero() {
    int i = blockIdx.x * blockDim.x + threadIdx.x;
    if (i < NG * HID) g_pool[i] = 0.f;
    if (i < NG) g_cnt[i] = 0.f;
}

__global__ void k_cnt(const int* __restrict__ batch) {
    int i = blockIdx.x * blockDim.x + threadIdx.x;
    if (i < N_NODES) atomicAdd(&g_cnt[batch[i]], 1.0f);
}

// batch is sorted: run-length accumulate per block, few atomics
__global__ void k_pool(const int* __restrict__ batch) {
    int j = threadIdx.x;  // 256
    int r0 = blockIdx.x * 64;
    int r1 = min(r0 + 64, N_NODES);
    if (r0 >= N_NODES) return;
    int cur = batch[r0];
    float acc = 0.f;
    for (int r = r0; r < r1; r++) {
        int bb = batch[r];
        if (bb != cur) {
            atomicAdd(&g_pool[cur * HID + j], acc);
            acc = 0.f;
            cur = bb;
        }
        acc += g_h[(size_t)r * HID + j];
    }
    atomicAdd(&g_pool[cur * HID + j], acc);
}

// ---- head: mean, lin1+relu, lin2 ----
__global__ void k_head(const float* __restrict__ l1w, const float* __restrict__ l1b,
                       const float* __restrict__ l2w, const float* __restrict__ l2b,
                       float* __restrict__ out) {
    __shared__ float gv[HID];
    __shared__ float red[4];
    int g = blockIdx.x, t = threadIdx.x;  // 128 threads
    float ic = 1.f / fmaxf(g_cnt[g], 1.f);
    gv[t] = g_pool[g * HID + t] * ic;
    gv[t + 128] = g_pool[g * HID + t + 128] * ic;
    __syncthreads();
    float acc = l1b[t];
#pragma unroll 8
    for (int k = 0; k < HID; k++) acc += gv[k] * l1w[k * 128 + t];
    acc = fmaxf(acc, 0.f) * l2w[t];
#pragma unroll
    for (int o = 16; o; o >>= 1) acc += __shfl_down_sync(0xffffffffu, acc, o);
    if ((t & 31) == 0) red[t >> 5] = acc;
    __syncthreads();
    if (t == 0) out[g] = red[0] + red[1] + red[2] + red[3] + l2b[0];
}

extern "C" void kernel_launch(void* const* d_in, const int* in_sizes, int n_in,
                              void* d_out, int out_size) {
    const float* x     = (const float*)d_in[0];
    const int* ei      = (const int*)d_in[1];   // int32 (JAX x32 mode)
    const int* bat     = (const int*)d_in[2];   // int32
    const float* W1 = (const float*)d_in[3];
    const float* b1 = (const float*)d_in[4];
    const float* Wl[3] = {(const float*)d_in[5], (const float*)d_in[7], (const float*)d_in[9]};
    const float* bl[3] = {(const float*)d_in[6], (const float*)d_in[8], (const float*)d_in[10]};
    const float* l1w = (const float*)d_in[11];
    const float* l1b = (const float*)d_in[12];
    const float* l2w = (const float*)d_in[13];
    const float* l2b = (const float*)d_in[14];
    float* out = (float*)d_out;

    k_init_deg<<<(N_NODES + 255) / 256, 256>>>();
    k_deg<<<(N_EDGES + 255) / 256, 256>>>(ei);
    k_rsqrt<<<(N_NODES + 255) / 256, 256>>>();

    // layer 1: aggregate-first (2-wide), then 2->256 transform
    k_prep_x<<<(N_NODES + 255) / 256, 256>>>(x);
    k_scat2<<<(N_EDGES + 255) / 256, 256>>>(ei);
    k_layer1<<<N_NODES, 256>>>(W1, b1);

    // layers 2..4
    for (int l = 0; l < 3; l++) {
        k_prep<<<(N_NODES * HID / 4 + 255) / 256, 256>>>();
        k_scat<<<N_EDGES / 8, 256>>>(ei);  // 1 warp per edge, 8 warps/block
        k_gemm<<<dim3(HID / 64, (N_NODES + 63) / 64), 256>>>(Wl[l], bl[l]);
    }

    // mean pool + MLP head
    k_pool_zero<<<(NG * HID + 255) / 256, 256>>>();
    k_cnt<<<(N_NODES + 255) / 256, 256>>>(bat);
    k_pool<<<(N_NODES + 63) / 64, 256>>>(bat);
    k_head<<<NG, 128>>>(l1w, l1b, l2w, l2b, out);
}

// round 4
// speedup vs baseline: 1.3600x; 1.3600x over previous
#include <cuda_runtime.h>
#include <cuda_bf16.h>

#define N_NODES 50000
#define N_EDGES 800000
#define HID 256
#define NG 128
#define NBLK 196          // ceil(N_NODES/256)

// ---- scratch (static device globals; no allocation) ----
__device__ int   g_deg[N_NODES];
__device__ int   g_rowptr[N_NODES];
__device__ int   g_cursor[N_NODES];
__device__ int   g_eidx[N_EDGES];
__device__ int   g_bsum[NBLK];
__device__ int   g_boff[NBLK];
__device__ float g_dinv[N_NODES];
__device__ float g_px[N_NODES * 2];
__device__ float g_aggx[N_NODES * 2];
__device__ float g_h[(size_t)N_NODES * HID];
__device__ float g_p[(size_t)N_NODES * HID];
__device__ float g_agg[(size_t)N_NODES * HID];
__device__ float g_pool[NG * HID];
__device__ float g_cnt[NG];

// ---- zero pass (deg, pool, cnt) — grid MUST cover N_NODES ----
__global__ void k_zero() {
    int i = blockIdx.x * blockDim.x + threadIdx.x;
    if (i < N_NODES) g_deg[i] = 0;
    if (i < NG * HID) g_pool[i] = 0.f;
    if (i < NG) g_cnt[i] = 0.f;
}

__global__ void k_count(const int* __restrict__ ei) {
    int e = blockIdx.x * blockDim.x + threadIdx.x;
    if (e < N_EDGES) atomicAdd(&g_deg[ei[N_EDGES + e]], 1);
}

__global__ void k_rsqrt() {
    int i = blockIdx.x * blockDim.x + threadIdx.x;
    if (i < N_NODES) g_dinv[i] = rsqrtf((float)g_deg[i] + 1.0f);  // +1 self-loop
}

// ---- CSR build: two-level exclusive scan of g_deg -> g_rowptr ----
__global__ void k_blocksum() {
    __shared__ int s[256];
    int t = threadIdx.x;
    int i = blockIdx.x * 256 + t;
    int v = (i < N_NODES) ? g_deg[i] : 0;
    s[t] = v; __syncthreads();
    for (int o = 128; o; o >>= 1) { if (t < o) s[t] += s[t + o]; __syncthreads(); }
    if (t == 0) g_bsum[blockIdx.x] = s[0];
}

__global__ void k_scanb() {  // single block, exclusive scan of NBLK block sums
    __shared__ int s[256];
    int t = threadIdx.x;
    int v = (t < NBLK) ? g_bsum[t] : 0;
    s[t] = v; __syncthreads();
    for (int o = 1; o < 256; o <<= 1) {
        int x = (t >= o) ? s[t - o] : 0; __syncthreads();
        s[t] += x; __syncthreads();
    }
    if (t < NBLK) g_boff[t] = s[t] - v;  // exclusive
}

__global__ void k_scan3() {
    __shared__ int s[256];
    int t = threadIdx.x;
    int i = blockIdx.x * 256 + t;
    int v = (i < N_NODES) ? g_deg[i] : 0;
    s[t] = v; __syncthreads();
    for (int o = 1; o < 256; o <<= 1) {
        int x = (t >= o) ? s[t - o] : 0; __syncthreads();
        s[t] += x; __syncthreads();
    }
    if (i < N_NODES) {
        int beg = g_boff[blockIdx.x] + s[t] - v;
        g_rowptr[i] = beg;
        g_cursor[i] = beg;
    }
}

__global__ void k_fill(const int* __restrict__ ei) {
    int e = blockIdx.x * blockDim.x + threadIdx.x;
    if (e < N_EDGES) {
        int d = ei[N_EDGES + e];
        int pos = atomicAdd(&g_cursor[d], 1);
        g_eidx[pos] = ei[e];
    }
}

// ---- layer 1: aggregate x (2-wide) BEFORE the 2->256 matmul ----
__global__ void k_prep_x(const float* __restrict__ x) {
    int i = blockIdx.x * blockDim.x + threadIdx.x;
    if (i < N_NODES) {
        float d = g_dinv[i];
        g_px[2 * i]     = d * x[2 * i];
        g_px[2 * i + 1] = d * x[2 * i + 1];
    }
}

__global__ void k_gather2() {  // thread per node, CSR gather of 2-wide px
    int i = blockIdx.x * blockDim.x + threadIdx.x;
    if (i < N_NODES) {
        int beg = g_rowptr[i], n = g_deg[i];
        float a = g_px[2 * i], b = g_px[2 * i + 1];  // self-loop
        for (int e = 0; e < n; e++) {
            int s = g_eidx[beg + e];
            a += g_px[2 * s];
            b += g_px[2 * s + 1];
        }
        g_aggx[2 * i] = a;
        g_aggx[2 * i + 1] = b;
    }
}

// p1[i][j] = relu(dinv*(aggx·W1col)+b1) * dinv   (fused transform + prep)
__global__ void k_layer1(const float* __restrict__ W1, const float* __restrict__ b1) {
    int i = blockIdx.x;
    int j = threadIdx.x;
    float d = g_dinv[i];
    float a0 = g_aggx[2 * i] * d;
    float a1 = g_aggx[2 * i + 1] * d;
    float h = a0 * W1[j] + a1 * W1[HID + j] + b1[j];
    g_p[(size_t)i * HID + j] = fmaxf(h, 0.f) * d;
}

// ---- CSR gather aggregation: 1 warp per dst node, 8 floats/lane ----
__global__ void k_gather() {
    int w = (blockIdx.x * blockDim.x + threadIdx.x) >> 5;
    int l = threadIdx.x & 31;
    if (w >= N_NODES) return;
    int beg = g_rowptr[w], n = g_deg[w];
    float acc[8];
    const float* pself = g_p + (size_t)w * HID;
#pragma unroll
    for (int i = 0; i < 8; i++) acc[i] = pself[l + i * 32];  // self-loop init
    for (int e = 0; e < n; e++) {
        int s = g_eidx[beg + e];  // broadcast load
        const float* ps = g_p + (size_t)s * HID;
#pragma unroll
        for (int i = 0; i < 8; i++) acc[i] += __ldg(ps + l + i * 32);
    }
    float* ad = g_agg + (size_t)w * HID;
#pragma unroll
    for (int i = 0; i < 8; i++) ad[l + i * 32] = acc[i];
}

// ---- SGEMM: out = (dinv ⊙ agg) @ W + bias, epilogue fused ----
// WRITE_P: out = relu(h)*dinv into g_p (layers 2,3); else h into g_h (layer 4)
template <bool WRITE_P>
__global__ void k_gemm(const float* __restrict__ W, const float* __restrict__ bias) {
    __shared__ float As[32][65];  // transposed A tile, padded
    __shared__ float Ws[32][64];
    int tx = threadIdx.x & 15;
    int ty = threadIdx.x >> 4;
    int rowBase = blockIdx.y * 64;
    int colBase = blockIdx.x * 64;
    float acc[4][4] = {};

    for (int k0 = 0; k0 < HID; k0 += 32) {
#pragma unroll
        for (int i = 0; i < 8; i++) {
            int li = threadIdx.x + i * 256;
            int r = li >> 5, kk = li & 31;
            int gr = rowBase + r;
            As[kk][r] = (gr < N_NODES) ? g_agg[(size_t)gr * HID + k0 + kk] : 0.f;
        }
#pragma unroll
        for (int i = 0; i < 8; i++) {
            int li = threadIdx.x + i * 256;
            int kk = li >> 6, c = li & 63;
            Ws[kk][c] = W[(size_t)(k0 + kk) * HID + colBase + c];
        }
        __syncthreads();
#pragma unroll
        for (int k = 0; k < 32; k++) {
            float a[4], b[4];
#pragma unroll
            for (int j = 0; j < 4; j++) { a[j] = As[k][ty * 4 + j]; b[j] = Ws[k][tx * 4 + j]; }
#pragma unroll
            for (int j = 0; j < 4; j++)
#pragma unroll
                for (int i = 0; i < 4; i++) acc[j][i] += a[j] * b[i];
        }
        __syncthreads();
    }

#pragma unroll
    for (int j = 0; j < 4; j++) {
        int r = rowBase + ty * 4 + j;
        if (r < N_NODES) {
            float d = g_dinv[r];
#pragma unroll
            for (int i = 0; i < 4; i++) {
                int c = colBase + tx * 4 + i;
                float h = d * acc[j][i] + bias[c];
                if (WRITE_P)
                    g_p[(size_t)r * HID + c] = fmaxf(h, 0.f) * d;
                else
                    g_h[(size_t)r * HID + c] = h;
            }
        }
    }
}

// ---- pooling ----
__global__ void k_cnt(const int* __restrict__ batch) {
    int i = blockIdx.x * blockDim.x + threadIdx.x;
    if (i < N_NODES) atomicAdd(&g_cnt[batch[i]], 1.0f);
}

// batch is sorted: run-length accumulate per block, few atomics
__global__ void k_pool(const int* __restrict__ batch) {
    int j = threadIdx.x;  // 256
    int r0 = blockIdx.x * 64;
    int r1 = min(r0 + 64, N_NODES);
    if (r0 >= N_NODES) return;
    int cur = batch[r0];
    float acc = 0.f;
    for (int r = r0; r < r1; r++) {
        int bb = batch[r];
        if (bb != cur) {
            atomicAdd(&g_pool[cur * HID + j], acc);
            acc = 0.f;
            cur = bb;
        }
        acc += g_h[(size_t)r * HID + j];
    }
    atomicAdd(&g_pool[cur * HID + j], acc);
}

// ---- head: mean, lin1+relu, lin2 ----
__global__ void k_head(const float* __restrict__ l1w, const float* __restrict__ l1b,
                       const float* __restrict__ l2w, const float* __restrict__ l2b,
                       float* __restrict__ out) {
    __shared__ float gv[HID];
    __shared__ float red[4];
    int g = blockIdx.x, t = threadIdx.x;  // 128 threads
    float ic = 1.f / fmaxf(g_cnt[g], 1.f);
    gv[t] = g_pool[g * HID + t] * ic;
    gv[t + 128] = g_pool[g * HID + t + 128] * ic;
    __syncthreads();
    float acc = l1b[t];
#pragma unroll 8
    for (int k = 0; k < HID; k++) acc += gv[k] * l1w[k * 128 + t];
    acc = fmaxf(acc, 0.f) * l2w[t];
#pragma unroll
    for (int o = 16; o; o >>= 1) acc += __shfl_down_sync(0xffffffffu, acc, o);
    if ((t & 31) == 0) red[t >> 5] = acc;
    __syncthreads();
    if (t == 0) out[g] = red[0] + red[1] + red[2] + red[3] + l2b[0];
}

extern "C" void kernel_launch(void* const* d_in, const int* in_sizes, int n_in,
                              void* d_out, int out_size) {
    const float* x     = (const float*)d_in[0];
    const int* ei      = (const int*)d_in[1];   // int32 (JAX x32 mode)
    const int* bat     = (const int*)d_in[2];   // int32
    const float* W1 = (const float*)d_in[3];
    const float* b1 = (const float*)d_in[4];
    const float* Wl[3] = {(const float*)d_in[5], (const float*)d_in[7], (const float*)d_in[9]};
    const float* bl[3] = {(const float*)d_in[6], (const float*)d_in[8], (const float*)d_in[10]};
    const float* l1w = (const float*)d_in[11];
    const float* l1b = (const float*)d_in[12];
    const float* l2w = (const float*)d_in[13];
    const float* l2b = (const float*)d_in[14];
    float* out = (float*)d_out;

    // degrees + norm + CSR (dst-major). k_zero must cover N_NODES!
    k_zero<<<(N_NODES + 255) / 256, 256>>>();
    k_count<<<(N_EDGES + 255) / 256, 256>>>(ei);
    k_rsqrt<<<(N_NODES + 255) / 256, 256>>>();
    k_blocksum<<<NBLK, 256>>>();
    k_scanb<<<1, 256>>>();
    k_scan3<<<NBLK, 256>>>();
    k_fill<<<(N_EDGES + 255) / 256, 256>>>(ei);

    // layer 1: aggregate-first (2-wide), then fused 2->256 transform + prep
    k_prep_x<<<(N_NODES + 255) / 256, 256>>>(x);
    k_gather2<<<(N_NODES + 255) / 256, 256>>>();
    k_layer1<<<N_NODES, 256>>>(W1, b1);

    // layers 2..4: CSR gather + GEMM with fused epilogue
    dim3 ggrid(HID / 64, (N_NODES + 63) / 64);
    k_gather<<<(N_NODES * 32 + 255) / 256, 256>>>();
    k_gemm<true><<<ggrid, 256>>>(Wl[0], bl[0]);
    k_gather<<<(N_NODES * 32 + 255) / 256, 256>>>();
    k_gemm<true><<<ggrid, 256>>>(Wl[1], bl[1]);
    k_gather<<<(N_NODES * 32 + 255) / 256, 256>>>();
    k_gemm<false><<<ggrid, 256>>>(Wl[2], bl[2]);

    // mean pool + MLP head
    k_cnt<<<(N_NODES + 255) / 256, 256>>>(bat);
    k_pool<<<(N_NODES + 63) / 64, 256>>>(bat);
    k_head<<<NG, 128>>>(l1w, l1b, l2w, l2b, out);
}

// round 5
// speedup vs baseline: 1.4522x; 1.0678x over previous
#include <cuda_runtime.h>
#include <cuda_bf16.h>

#define N_NODES 50000
#define N_EDGES 800000
#define HID 256
#define NG 128

// ---- scratch (static device globals; no allocation) ----
__device__ int   g_deg[N_NODES];
__device__ int   g_rowptr[N_NODES];
__device__ int   g_cursor[N_NODES];
__device__ int   g_eidx[N_EDGES];
__device__ float g_dinv[N_NODES];
__device__ float g_px[N_NODES * 2];
__device__ float g_h[(size_t)N_NODES * HID];
__device__ float g_p[(size_t)N_NODES * HID];
__device__ float g_agg[(size_t)N_NODES * HID];
__device__ float g_pool[NG * HID];

// ---- zero degrees (must cover N_NODES; runs every call for determinism) ----
__global__ void k_zero() {
    int i = blockIdx.x * blockDim.x + threadIdx.x;
    if (i < N_NODES) g_deg[i] = 0;
}

__global__ void k_count(const int* __restrict__ ei) {
    int e = blockIdx.x * blockDim.x + threadIdx.x;
    if (e < N_EDGES) atomicAdd(&g_deg[ei[N_EDGES + e]], 1);
}

// dinv = rsqrt(deg+1); px = dinv * x  (fused)
__global__ void k_rsqrt_px(const float* __restrict__ x) {
    int i = blockIdx.x * blockDim.x + threadIdx.x;
    if (i < N_NODES) {
        float d = rsqrtf((float)g_deg[i] + 1.0f);
        g_dinv[i] = d;
        float2 v = ((const float2*)x)[i];
        float2 o; o.x = d * v.x; o.y = d * v.y;
        ((float2*)g_px)[i] = o;
    }
}

// ---- single-block exclusive scan of g_deg -> g_rowptr/g_cursor ----
__global__ void k_scan() {  // 1024 threads, one block
    __shared__ int s[1024];
    const int CH = (N_NODES + 1023) / 1024;  // 49
    int t = threadIdx.x;
    int base = t * CH;
    int sum = 0;
    for (int j = 0; j < CH; j++) {
        int i = base + j;
        if (i < N_NODES) sum += g_deg[i];
    }
    s[t] = sum; __syncthreads();
    for (int o = 1; o < 1024; o <<= 1) {
        int v = (t >= o) ? s[t - o] : 0;
        __syncthreads();
        s[t] += v;
        __syncthreads();
    }
    int run = s[t] - sum;  // exclusive prefix
    for (int j = 0; j < CH; j++) {
        int i = base + j;
        if (i < N_NODES) {
            g_rowptr[i] = run;
            g_cursor[i] = run;
            run += g_deg[i];
        }
    }
}

__global__ void k_fill(const int* __restrict__ ei) {
    int e = blockIdx.x * blockDim.x + threadIdx.x;
    if (e < N_EDGES) {
        int d = ei[N_EDGES + e];
        int pos = atomicAdd(&g_cursor[d], 1);
        g_eidx[pos] = ei[e];
    }
}

// ---- layer 1: block per node. warp 0 gathers 2-wide aggx, then fused
//      transform: p1 = relu(dinv*(aggx . W1col)+b1) * dinv ----
__global__ void k_layer1(const float* __restrict__ W1, const float* __restrict__ b1) {
    __shared__ float sa[2];
    int i = blockIdx.x;
    int t = threadIdx.x;  // 256
    if (t < 32) {
        int beg = g_rowptr[i], n = g_deg[i];
        float a = 0.f, b = 0.f;
        for (int e = t; e < n; e += 32) {
            int s = g_eidx[beg + e];
            a += g_px[2 * s];
            b += g_px[2 * s + 1];
        }
#pragma unroll
        for (int o = 16; o; o >>= 1) {
            a += __shfl_down_sync(0xffffffffu, a, o);
            b += __shfl_down_sync(0xffffffffu, b, o);
        }
        if (t == 0) { sa[0] = a + g_px[2 * i]; sa[1] = b + g_px[2 * i + 1]; }
    }
    __syncthreads();
    float d = g_dinv[i];
    float a0 = sa[0] * d;
    float a1 = sa[1] * d;
    float h = a0 * W1[t] + a1 * W1[HID + t] + b1[t];
    g_p[(size_t)i * HID + t] = fmaxf(h, 0.f) * d;
}

// ---- CSR gather aggregation: 1 warp per dst node, 8 floats/lane,
//      edge-pair unrolled for MLP ----
__global__ void k_gather() {
    int w = (blockIdx.x * blockDim.x + threadIdx.x) >> 5;
    int l = threadIdx.x & 31;
    if (w >= N_NODES) return;
    int beg = g_rowptr[w], n = g_deg[w];
    float acc[8];
    const float* pself = g_p + (size_t)w * HID;
#pragma unroll
    for (int i = 0; i < 8; i++) acc[i] = pself[l + i * 32];  // self-loop init
    int e = 0;
    for (; e + 2 <= n; e += 2) {
        int s0 = g_eidx[beg + e];
        int s1 = g_eidx[beg + e + 1];
        const float* p0 = g_p + (size_t)s0 * HID;
        const float* p1 = g_p + (size_t)s1 * HID;
#pragma unroll
        for (int i = 0; i < 8; i++)
            acc[i] += __ldg(p0 + l + i * 32) + __ldg(p1 + l + i * 32);
    }
    if (e < n) {
        int s0 = g_eidx[beg + e];
        const float* p0 = g_p + (size_t)s0 * HID;
#pragma unroll
        for (int i = 0; i < 8; i++) acc[i] += __ldg(p0 + l + i * 32);
    }
    float* ad = g_agg + (size_t)w * HID;
#pragma unroll
    for (int i = 0; i < 8; i++) ad[l + i * 32] = acc[i];
}

// ---- SGEMM 128x128 tile, 8x8 microtile: out = (dinv⊙agg)@W + bias ----
// WRITE_P: out = relu(h)*dinv into g_p (layers 2,3); else h into g_h (layer 4)
template <bool WRITE_P>
__global__ void __launch_bounds__(256, 2) k_gemm(const float* __restrict__ W,
                                                 const float* __restrict__ bias) {
    __shared__ float As[32][132];  // transposed A tile, padded (132%4==0)
    __shared__ float Ws[32][128];
    int tid = threadIdx.x;
    int tx = tid & 15;
    int ty = tid >> 4;
    int rowBase = blockIdx.y * 128;
    int colBase = blockIdx.x * 128;
    float acc[8][8] = {};

    for (int k0 = 0; k0 < HID; k0 += 32) {
        // A tile: 128 rows x 32 K as float4, transposed into smem
        {
            int col = tid & 7;        // float4 col 0..7
            int row0 = tid >> 3;      // 0..31
#pragma unroll
            for (int i = 0; i < 4; i++) {
                int r = row0 + i * 32;
                int gr = rowBase + r;
                float4 v = (gr < N_NODES)
                    ? *(const float4*)&g_agg[(size_t)gr * HID + k0 + col * 4]
                    : make_float4(0.f, 0.f, 0.f, 0.f);
                As[col * 4 + 0][r] = v.x;
                As[col * 4 + 1][r] = v.y;
                As[col * 4 + 2][r] = v.z;
                As[col * 4 + 3][r] = v.w;
            }
        }
        // W tile: 32 K x 128 cols as float4
        {
            int col = (tid & 31) * 4;
            int k1 = tid >> 5;        // 0..7
#pragma unroll
            for (int i = 0; i < 4; i++) {
                int kk = k1 + i * 8;
                *(float4*)&Ws[kk][col] =
                    *(const float4*)&W[(size_t)(k0 + kk) * HID + colBase + col];
            }
        }
        __syncthreads();
#pragma unroll
        for (int k = 0; k < 32; k++) {
            float a[8], b[8];
            *(float4*)&a[0] = *(const float4*)&As[k][ty * 4];
            *(float4*)&a[4] = *(const float4*)&As[k][64 + ty * 4];
            *(float4*)&b[0] = *(const float4*)&Ws[k][tx * 4];
            *(float4*)&b[4] = *(const float4*)&Ws[k][64 + tx * 4];
#pragma unroll
            for (int j = 0; j < 8; j++)
#pragma unroll
                for (int i = 0; i < 8; i++) acc[j][i] += a[j] * b[i];
        }
        __syncthreads();
    }

    float4 bs0 = *(const float4*)&bias[colBase + tx * 4];
    float4 bs1 = *(const float4*)&bias[colBase + 64 + tx * 4];
#pragma unroll
    for (int jj = 0; jj < 8; jj++) {
        int r = rowBase + (jj < 4 ? ty * 4 + jj : 64 + ty * 4 + (jj - 4));
        if (r < N_NODES) {
            float d = g_dinv[r];
            float4 o0, o1;
            o0.x = d * acc[jj][0] + bs0.x;
            o0.y = d * acc[jj][1] + bs0.y;
            o0.z = d * acc[jj][2] + bs0.z;
            o0.w = d * acc[jj][3] + bs0.w;
            o1.x = d * acc[jj][4] + bs1.x;
            o1.y = d * acc[jj][5] + bs1.y;
            o1.z = d * acc[jj][6] + bs1.z;
            o1.w = d * acc[jj][7] + bs1.w;
            if (WRITE_P) {
                o0.x = fmaxf(o0.x, 0.f) * d; o0.y = fmaxf(o0.y, 0.f) * d;
                o0.z = fmaxf(o0.z, 0.f) * d; o0.w = fmaxf(o0.w, 0.f) * d;
                o1.x = fmaxf(o1.x, 0.f) * d; o1.y = fmaxf(o1.y, 0.f) * d;
                o1.z = fmaxf(o1.z, 0.f) * d; o1.w = fmaxf(o1.w, 0.f) * d;
                *(float4*)&g_p[(size_t)r * HID + colBase + tx * 4] = o0;
                *(float4*)&g_p[(size_t)r * HID + colBase + 64 + tx * 4] = o1;
            } else {
                *(float4*)&g_h[(size_t)r * HID + colBase + tx * 4] = o0;
                *(float4*)&g_h[(size_t)r * HID + colBase + 64 + tx * 4] = o1;
            }
        }
    }
}

// ---- mean pool: block per graph, binary-search bounds (batch sorted),
//      no atomics, writes the MEAN directly ----
__global__ void k_pool(const int* __restrict__ batch) {
    int g = blockIdx.x;
    int j = threadIdx.x;  // 256
    int a = 0, b = N_NODES;
    while (a < b) { int m = (a + b) >> 1; if (batch[m] < g) a = m + 1; else b = m; }
    int lo = a;
    b = N_NODES;
    while (a < b) { int m = (a + b) >> 1; if (batch[m] < g + 1) a = m + 1; else b = m; }
    int hi = a;
    float acc = 0.f;
    for (int r = lo; r < hi; r++) acc += g_h[(size_t)r * HID + j];
    g_pool[g * HID + j] = acc / fmaxf((float)(hi - lo), 1.f);
}

// ---- head: lin1+relu, lin2 (pool already holds means) ----
__global__ void k_head(const float* __restrict__ l1w, const float* __restrict__ l1b,
                       const float* __restrict__ l2w, const float* __restrict__ l2b,
                       float* __restrict__ out) {
    __shared__ float gv[HID];
    __shared__ float red[4];
    int g = blockIdx.x, t = threadIdx.x;  // 128 threads
    gv[t] = g_pool[g * HID + t];
    gv[t + 128] = g_pool[g * HID + t + 128];
    __syncthreads();
    float acc = l1b[t];
#pragma unroll 8
    for (int k = 0; k < HID; k++) acc += gv[k] * l1w[k * 128 + t];
    acc = fmaxf(acc, 0.f) * l2w[t];
#pragma unroll
    for (int o = 16; o; o >>= 1) acc += __shfl_down_sync(0xffffffffu, acc, o);
    if ((t & 31) == 0) red[t >> 5] = acc;
    __syncthreads();
    if (t == 0) out[g] = red[0] + red[1] + red[2] + red[3] + l2b[0];
}

extern "C" void kernel_launch(void* const* d_in, const int* in_sizes, int n_in,
                              void* d_out, int out_size) {
    const float* x     = (const float*)d_in[0];
    const int* ei      = (const int*)d_in[1];   // int32 (JAX x32 mode)
    const int* bat     = (const int*)d_in[2];   // int32
    const float* W1 = (const float*)d_in[3];
    const float* b1 = (const float*)d_in[4];
    const float* Wl[3] = {(const float*)d_in[5], (const float*)d_in[7], (const float*)d_in[9]};
    const float* bl[3] = {(const float*)d_in[6], (const float*)d_in[8], (const float*)d_in[10]};
    const float* l1w = (const float*)d_in[11];
    const float* l1b = (const float*)d_in[12];
    const float* l2w = (const float*)d_in[13];
    const float* l2b = (const float*)d_in[14];
    float* out = (float*)d_out;

    // degrees + norm + CSR (dst-major)
    k_zero<<<(N_NODES + 255) / 256, 256>>>();
    k_count<<<(N_EDGES + 255) / 256, 256>>>(ei);
    k_rsqrt_px<<<(N_NODES + 255) / 256, 256>>>(x);
    k_scan<<<1, 1024>>>();
    k_fill<<<(N_EDGES + 255) / 256, 256>>>(ei);

    // layer 1: fused 2-wide gather + 2->256 transform + relu*dinv prep
    k_layer1<<<N_NODES, 256>>>(W1, b1);

    // layers 2..4: CSR gather + 128x128 GEMM with fused epilogue
    dim3 ggrid(HID / 128, (N_NODES + 127) / 128);
    k_gather<<<(N_NODES * 32 + 255) / 256, 256>>>();
    k_gemm<true><<<ggrid, 256>>>(Wl[0], bl[0]);
    k_gather<<<(N_NODES * 32 + 255) / 256, 256>>>();
    k_gemm<true><<<ggrid, 256>>>(Wl[1], bl[1]);
    k_gather<<<(N_NODES * 32 + 255) / 256, 256>>>();
    k_gemm<false><<<ggrid, 256>>>(Wl[2], bl[2]);

    // mean pool (no atomics) + MLP head
    k_pool<<<NG, 256>>>(bat);
    k_head<<<NG, 128>>>(l1w, l1b, l2w, l2b, out);
}

// round 8
// speedup vs baseline: 2.3528x; 1.6202x over previous
#include <cuda_runtime.h>
#include <cuda_bf16.h>
#include <cstdint>

#define N_NODES 50000
#define N_EDGES 800000
#define HID 256
#define NG 128
#define NBLK 196          // ceil(N_NODES/256)

// ---- scratch (static device globals; no allocation) ----
__device__ int   g_deg[N_NODES];
__device__ int   g_rowptr[N_NODES];
__device__ int   g_cursor[N_NODES];
__device__ int   g_eidx[N_EDGES];
__device__ int   g_bsum[NBLK];
__device__ int   g_boff[NBLK];
__device__ float g_dinv[N_NODES];
__device__ float g_px[N_NODES * 2];
__device__ float g_h[(size_t)N_NODES * HID];
__device__ float g_p[(size_t)N_NODES * HID];
__device__ float g_agg[(size_t)N_NODES * HID];
__device__ float g_pool[NG * HID];

__device__ __forceinline__ uint32_t f2tf32(float x) {
    uint32_t r;
    asm("cvt.rna.tf32.f32 %0, %1;" : "=r"(r) : "f"(x));
    return r;
}

// ---- zero degrees ----
__global__ void k_zero() {
    int i = blockIdx.x * blockDim.x + threadIdx.x;
    if (i < N_NODES) g_deg[i] = 0;
}

__global__ void k_count(const int* __restrict__ ei) {
    int e = blockIdx.x * blockDim.x + threadIdx.x;
    if (e < N_EDGES) atomicAdd(&g_deg[ei[N_EDGES + e]], 1);
}

// dinv = rsqrt(deg+1); px = dinv * x  (fused)
__global__ void k_rsqrt_px(const float* __restrict__ x) {
    int i = blockIdx.x * blockDim.x + threadIdx.x;
    if (i < N_NODES) {
        float d = rsqrtf((float)g_deg[i] + 1.0f);
        g_dinv[i] = d;
        float2 v = ((const float2*)x)[i];
        float2 o; o.x = d * v.x; o.y = d * v.y;
        ((float2*)g_px)[i] = o;
    }
}

// ---- CSR build: parallel two-level exclusive scan ----
__global__ void k_blocksum() {
    __shared__ int s[256];
    int t = threadIdx.x;
    int i = blockIdx.x * 256 + t;
    int v = (i < N_NODES) ? g_deg[i] : 0;
    s[t] = v; __syncthreads();
    for (int o = 128; o; o >>= 1) { if (t < o) s[t] += s[t + o]; __syncthreads(); }
    if (t == 0) g_bsum[blockIdx.x] = s[0];
}

__global__ void k_scanb() {  // single block, exclusive scan of NBLK block sums
    __shared__ int s[256];
    int t = threadIdx.x;
    int v = (t < NBLK) ? g_bsum[t] : 0;
    s[t] = v; __syncthreads();
    for (int o = 1; o < 256; o <<= 1) {
        int x = (t >= o) ? s[t - o] : 0; __syncthreads();
        s[t] += x; __syncthreads();
    }
    if (t < NBLK) g_boff[t] = s[t] - v;  // exclusive
}

__global__ void k_scan3() {
    __shared__ int s[256];
    int t = threadIdx.x;
    int i = blockIdx.x * 256 + t;
    int v = (i < N_NODES) ? g_deg[i] : 0;
    s[t] = v; __syncthreads();
    for (int o = 1; o < 256; o <<= 1) {
        int x = (t >= o) ? s[t - o] : 0; __syncthreads();
        s[t] += x; __syncthreads();
    }
    if (i < N_NODES) {
        int beg = g_boff[blockIdx.x] + s[t] - v;
        g_rowptr[i] = beg;
        g_cursor[i] = beg;
    }
}

__global__ void k_fill(const int* __restrict__ ei) {
    int e = blockIdx.x * blockDim.x + threadIdx.x;
    if (e < N_EDGES) {
        int d = ei[N_EDGES + e];
        int pos = atomicAdd(&g_cursor[d], 1);
        g_eidx[pos] = ei[e];
    }
}

// ---- layer 1: block per node; warp 0 gathers 2-wide, fused transform ----
__global__ void k_layer1(const float* __restrict__ W1, const float* __restrict__ b1) {
    __shared__ float sa[2];
    int i = blockIdx.x;
    int t = threadIdx.x;  // 256
    if (t < 32) {
        int beg = g_rowptr[i], n = g_deg[i];
        float a = 0.f, b = 0.f;
        for (int e = t; e < n; e += 32) {
            int s = g_eidx[beg + e];
            a += g_px[2 * s];
            b += g_px[2 * s + 1];
        }
#pragma unroll
        for (int o = 16; o; o >>= 1) {
            a += __shfl_down_sync(0xffffffffu, a, o);
            b += __shfl_down_sync(0xffffffffu, b, o);
        }
        if (t == 0) { sa[0] = a + g_px[2 * i]; sa[1] = b + g_px[2 * i + 1]; }
    }
    __syncthreads();
    float d = g_dinv[i];
    float a0 = sa[0] * d;
    float a1 = sa[1] * d;
    float h = a0 * W1[t] + a1 * W1[HID + t] + b1[t];
    g_p[(size_t)i * HID + t] = fmaxf(h, 0.f) * d;
}

// ---- CSR gather: 1 warp per dst node, 8 floats/lane, pair-unrolled ----
__global__ void k_gather() {
    int w = (blockIdx.x * blockDim.x + threadIdx.x) >> 5;
    int l = threadIdx.x & 31;
    if (w >= N_NODES) return;
    int beg = g_rowptr[w], n = g_deg[w];
    float acc[8];
    const float* pself = g_p + (size_t)w * HID;
#pragma unroll
    for (int i = 0; i < 8; i++) acc[i] = pself[l + i * 32];  // self-loop init
    int e = 0;
    for (; e + 2 <= n; e += 2) {
        int s0 = g_eidx[beg + e];
        int s1 = g_eidx[beg + e + 1];
        const float* p0 = g_p + (size_t)s0 * HID;
        const float* p1 = g_p + (size_t)s1 * HID;
#pragma unroll
        for (int i = 0; i < 8; i++)
            acc[i] += __ldg(p0 + l + i * 32) + __ldg(p1 + l + i * 32);
    }
    if (e < n) {
        int s0 = g_eidx[beg + e];
        const float* p0 = g_p + (size_t)s0 * HID;
#pragma unroll
        for (int i = 0; i < 8; i++) acc[i] += __ldg(p0 + l + i * 32);
    }
    float* ad = g_agg + (size_t)w * HID;
#pragma unroll
    for (int i = 0; i < 8; i++) ad[l + i * 32] = acc[i];
}

// ---- TF32 tensor-core GEMM: out = (dinv⊙agg)@W + bias ----
// Block 128x128, 8 warps (2 M x 4 N), warp tile 64x32 as 4x4 mma m16n8k8.
// WRITE_P: out = relu(h)*dinv into g_p; else h into g_h.
#define AS_STRIDE 36   // 32 + 4 pad -> A-frag banks = 4g+q  (conflict-free)
#define BS_STRIDE 136  // 128 + 8 pad -> B-frag banks = 8q+g (conflict-free)
template <bool WRITE_P>
__global__ void __launch_bounds__(256, 2) k_gemm(const float* __restrict__ W,
                                                 const float* __restrict__ bias) {
    __shared__ uint32_t As[128 * AS_STRIDE];  // [m][k] tf32, 18432 B
    __shared__ uint32_t Bs[32 * BS_STRIDE];   // [k][n] tf32, 17408 B
    int tid = threadIdx.x;
    int lane = tid & 31;
    int warp = tid >> 5;
    int warp_m = warp & 1;        // 0..1
    int warp_n = warp >> 1;       // 0..3
    int g = lane >> 2;            // 0..7
    int q = lane & 3;             // 0..3
    int rowBase = blockIdx.y * 128;
    int colBase = blockIdx.x * 128;

    float c[4][4][4];             // [mi][ni][reg]
#pragma unroll
    for (int mi = 0; mi < 4; mi++)
#pragma unroll
        for (int ni = 0; ni < 4; ni++)
#pragma unroll
            for (int r = 0; r < 4; r++) c[mi][ni][r] = 0.f;

    for (int k0 = 0; k0 < HID; k0 += 32) {
        // A tile: 128x32 floats -> tf32, [m][k] padded
        {
            int m0 = tid >> 3;          // 0..31
            int kq = (tid & 7) * 4;     // 0,4,..28
#pragma unroll
            for (int i = 0; i < 4; i++) {
                int m = m0 + i * 32;
                int gr = rowBase + m;
                float4 v = (gr < N_NODES)
                    ? *(const float4*)&g_agg[(size_t)gr * HID + k0 + kq]
                    : make_float4(0.f, 0.f, 0.f, 0.f);
                uint32_t* dst = &As[m * AS_STRIDE + kq];
                dst[0] = f2tf32(v.x); dst[1] = f2tf32(v.y);
                dst[2] = f2tf32(v.z); dst[3] = f2tf32(v.w);
            }
        }
        // B tile: 32 k x 128 n floats -> tf32, [k][n] padded
        {
            int kk = tid >> 3;          // 0..31
            int nq = (tid & 7) * 4;
#pragma unroll
            for (int i = 0; i < 4; i++) {
                int n = nq + i * 32;
                float4 v = *(const float4*)&W[(size_t)(k0 + kk) * HID + colBase + n];
                uint32_t* dst = &Bs[kk * BS_STRIDE + n];
                dst[0] = f2tf32(v.x); dst[1] = f2tf32(v.y);
                dst[2] = f2tf32(v.z); dst[3] = f2tf32(v.w);
            }
        }
        __syncthreads();

#pragma unroll
        for (int ks = 0; ks < 4; ks++) {   // 4 k-steps of 8
            int kb = ks * 8;
            uint32_t a[4][4], b[4][2];
#pragma unroll
            for (int mi = 0; mi < 4; mi++) {
                int m = warp_m * 64 + mi * 16;
                const uint32_t* ap = &As[(m + g) * AS_STRIDE + kb + q];
                a[mi][0] = ap[0];
                a[mi][1] = ap[8 * AS_STRIDE];
                a[mi][2] = ap[4];
                a[mi][3] = ap[8 * AS_STRIDE + 4];
            }
#pragma unroll
            for (int ni = 0; ni < 4; ni++) {
                int n = warp_n * 32 + ni * 8;
                const uint32_t* bp = &Bs[(kb + q) * BS_STRIDE + n + g];
                b[ni][0] = bp[0];
                b[ni][1] = bp[4 * BS_STRIDE];
            }
#pragma unroll
            for (int mi = 0; mi < 4; mi++)
#pragma unroll
                for (int ni = 0; ni < 4; ni++) {
                    asm volatile(
                        "mma.sync.aligned.m16n8k8.row.col.f32.tf32.tf32.f32 "
                        "{%0,%1,%2,%3}, {%4,%5,%6,%7}, {%8,%9}, {%0,%1,%2,%3};"
                        : "+f"(c[mi][ni][0]), "+f"(c[mi][ni][1]),
                          "+f"(c[mi][ni][2]), "+f"(c[mi][ni][3])
                        : "r"(a[mi][0]), "r"(a[mi][1]), "r"(a[mi][2]), "r"(a[mi][3]),
                          "r"(b[ni][0]), "r"(b[ni][1]));
                }
        }
        __syncthreads();
    }

    // epilogue: c[mi][ni] regs map to rows (m+g, m+g+8), cols (n+2q, n+2q+1)
#pragma unroll
    for (int mi = 0; mi < 4; mi++) {
#pragma unroll
        for (int half = 0; half < 2; half++) {
            int r = rowBase + warp_m * 64 + mi * 16 + g + half * 8;
            if (r >= N_NODES) continue;
            float d = g_dinv[r];
#pragma unroll
            for (int ni = 0; ni < 4; ni++) {
                int cc = colBase + warp_n * 32 + ni * 8 + 2 * q;
                float v0 = d * c[mi][ni][half * 2 + 0] + bias[cc];
                float v1 = d * c[mi][ni][half * 2 + 1] + bias[cc + 1];
                if (WRITE_P) {
                    v0 = fmaxf(v0, 0.f) * d;
                    v1 = fmaxf(v1, 0.f) * d;
                    *(float2*)&g_p[(size_t)r * HID + cc] = make_float2(v0, v1);
                } else {
                    *(float2*)&g_h[(size_t)r * HID + cc] = make_float2(v0, v1);
                }
            }
        }
    }
}

// ---- mean pool: block per graph, binary-search bounds (batch sorted) ----
__global__ void k_pool(const int* __restrict__ batch) {
    int g = blockIdx.x;
    int j = threadIdx.x;  // 256
    int a = 0, b = N_NODES;
    while (a < b) { int m = (a + b) >> 1; if (batch[m] < g) a = m + 1; else b = m; }
    int lo = a;
    b = N_NODES;
    while (a < b) { int m = (a + b) >> 1; if (batch[m] < g + 1) a = m + 1; else b = m; }
    int hi = a;
    float acc = 0.f;
    for (int r = lo; r < hi; r++) acc += g_h[(size_t)r * HID + j];
    g_pool[g * HID + j] = acc / fmaxf((float)(hi - lo), 1.f);
}

// ---- head: lin1+relu, lin2 ----
__global__ void k_head(const float* __restrict__ l1w, const float* __restrict__ l1b,
                       const float* __restrict__ l2w, const float* __restrict__ l2b,
                       float* __restrict__ out) {
    __shared__ float gv[HID];
    __shared__ float red[4];
    int g = blockIdx.x, t = threadIdx.x;  // 128 threads
    gv[t] = g_pool[g * HID + t];
    gv[t + 128] = g_pool[g * HID + t + 128];
    __syncthreads();
    float acc = l1b[t];
#pragma unroll 8
    for (int k = 0; k < HID; k++) acc += gv[k] * l1w[k * 128 + t];
    acc = fmaxf(acc, 0.f) * l2w[t];
#pragma unroll
    for (int o = 16; o; o >>= 1) acc += __shfl_down_sync(0xffffffffu, acc, o);
    if ((t & 31) == 0) red[t >> 5] = acc;
    __syncthreads();
    if (t == 0) out[g] = red[0] + red[1] + red[2] + red[3] + l2b[0];
}

extern "C" void kernel_launch(void* const* d_in, const int* in_sizes, int n_in,
                              void* d_out, int out_size) {
    const float* x     = (const float*)d_in[0];
    const int* ei      = (const int*)d_in[1];   // int32 (JAX x32 mode)
    const int* bat     = (const int*)d_in[2];   // int32
    const float* W1 = (const float*)d_in[3];
    const float* b1 = (const float*)d_in[4];
    const float* Wl[3] = {(const float*)d_in[5], (const float*)d_in[7], (const float*)d_in[9]};
    const float* bl[3] = {(const float*)d_in[6], (const float*)d_in[8], (const float*)d_in[10]};
    const float* l1w = (const float*)d_in[11];
    const float* l1b = (const float*)d_in[12];
    const float* l2w = (const float*)d_in[13];
    const float* l2b = (const float*)d_in[14];
    float* out = (float*)d_out;

    // degrees + norm + CSR (dst-major), parallel scan
    k_zero<<<(N_NODES + 255) / 256, 256>>>();
    k_count<<<(N_EDGES + 255) / 256, 256>>>(ei);
    k_rsqrt_px<<<(N_NODES + 255) / 256, 256>>>(x);
    k_blocksum<<<NBLK, 256>>>();
    k_scanb<<<1, 256>>>();
    k_scan3<<<NBLK, 256>>>();
    k_fill<<<(N_EDGES + 255) / 256, 256>>>(ei);

    // layer 1: fused 2-wide gather + 2->256 transform + relu*dinv prep
    k_layer1<<<N_NODES, 256>>>(W1, b1);

    // layers 2..4: CSR gather + tf32 tensor-core GEMM with fused epilogue
    dim3 ggrid(HID / 128, (N_NODES + 127) / 128);
    k_gather<<<(N_NODES * 32 + 255) / 256, 256>>>();
    k_gemm<true><<<ggrid, 256>>>(Wl[0], bl[0]);
    k_gather<<<(N_NODES * 32 + 255) / 256, 256>>>();
    k_gemm<true><<<ggrid, 256>>>(Wl[1], bl[1]);
    k_gather<<<(N_NODES * 32 + 255) / 256, 256>>>();
    k_gemm<false><<<ggrid, 256>>>(Wl[2], bl[2]);

    // mean pool (no atomics) + MLP head
    k_pool<<<NG, 256>>>(bat);
    k_head<<<NG, 128>>>(l1w, l1b, l2w, l2b, out);
}

// round 10
// speedup vs baseline: 2.4205x; 1.0288x over previous
#include <cuda_runtime.h>
#include <cuda_bf16.h>
#include <cstdint>

#define N_NODES 50000
#define N_EDGES 800000
#define HID 256
#define NG 128
#define NBLK 196          // ceil(N_NODES/256)

// ---- scratch (static device globals; no allocation) ----
__device__ int   g_deg[N_NODES];
__device__ int   g_rowptr[N_NODES];
__device__ int   g_cursor[N_NODES];
__device__ int   g_eidx[N_EDGES];
__device__ int   g_bsum[NBLK];
__device__ int   g_boff[NBLK];
__device__ float g_dinv[N_NODES];
__device__ float g_px[N_NODES * 2];
__device__ float g_h[(size_t)N_NODES * HID];
__device__ float g_p[(size_t)N_NODES * HID];
__device__ float g_agg[(size_t)N_NODES * HID];
__device__ float g_pool[NG * HID];

__device__ __forceinline__ uint32_t f2tf32(float x) {
    uint32_t r;
    asm("cvt.rna.tf32.f32 %0, %1;" : "=r"(r) : "f"(x));
    return r;
}

// ---- zero degrees ----
__global__ void k_zero() {
    int i = blockIdx.x * blockDim.x + threadIdx.x;
    if (i < N_NODES) g_deg[i] = 0;
}

__global__ void k_count(const int* __restrict__ ei) {
    int e = blockIdx.x * blockDim.x + threadIdx.x;
    if (e < N_EDGES) atomicAdd(&g_deg[ei[N_EDGES + e]], 1);
}

// dinv = rsqrt(deg+1); px = dinv * x  (fused)
__global__ void k_rsqrt_px(const float* __restrict__ x) {
    int i = blockIdx.x * blockDim.x + threadIdx.x;
    if (i < N_NODES) {
        float d = rsqrtf((float)g_deg[i] + 1.0f);
        g_dinv[i] = d;
        float2 v = ((const float2*)x)[i];
        float2 o; o.x = d * v.x; o.y = d * v.y;
        ((float2*)g_px)[i] = o;
    }
}

// ---- CSR build: parallel two-level exclusive scan ----
__global__ void k_blocksum() {
    __shared__ int s[256];
    int t = threadIdx.x;
    int i = blockIdx.x * 256 + t;
    int v = (i < N_NODES) ? g_deg[i] : 0;
    s[t] = v; __syncthreads();
    for (int o = 128; o; o >>= 1) { if (t < o) s[t] += s[t + o]; __syncthreads(); }
    if (t == 0) g_bsum[blockIdx.x] = s[0];
}

__global__ void k_scanb() {  // single block, exclusive scan of NBLK block sums
    __shared__ int s[256];
    int t = threadIdx.x;
    int v = (t < NBLK) ? g_bsum[t] : 0;
    s[t] = v; __syncthreads();
    for (int o = 1; o < 256; o <<= 1) {
        int x = (t >= o) ? s[t - o] : 0; __syncthreads();
        s[t] += x; __syncthreads();
    }
    if (t < NBLK) g_boff[t] = s[t] - v;  // exclusive
}

__global__ void k_scan3() {
    __shared__ int s[256];
    int t = threadIdx.x;
    int i = blockIdx.x * 256 + t;
    int v = (i < N_NODES) ? g_deg[i] : 0;
    s[t] = v; __syncthreads();
    for (int o = 1; o < 256; o <<= 1) {
        int x = (t >= o) ? s[t - o] : 0; __syncthreads();
        s[t] += x; __syncthreads();
    }
    if (i < N_NODES) {
        int beg = g_boff[blockIdx.x] + s[t] - v;
        g_rowptr[i] = beg;
        g_cursor[i] = beg;
    }
}

__global__ void k_fill(const int* __restrict__ ei) {
    int e = blockIdx.x * blockDim.x + threadIdx.x;
    if (e < N_EDGES) {
        int d = ei[N_EDGES + e];
        int pos = atomicAdd(&g_cursor[d], 1);
        g_eidx[pos] = ei[e];
    }
}

// ---- layer 1: block per node; warp 0 gathers 2-wide, fused transform ----
__global__ void k_layer1(const float* __restrict__ W1, const float* __restrict__ b1) {
    __shared__ float sa[2];
    int i = blockIdx.x;
    int t = threadIdx.x;  // 256
    if (t < 32) {
        int beg = g_rowptr[i], n = g_deg[i];
        float a = 0.f, b = 0.f;
        for (int e = t; e < n; e += 32) {
            int s = g_eidx[beg + e];
            a += g_px[2 * s];
            b += g_px[2 * s + 1];
        }
#pragma unroll
        for (int o = 16; o; o >>= 1) {
            a += __shfl_down_sync(0xffffffffu, a, o);
            b += __shfl_down_sync(0xffffffffu, b, o);
        }
        if (t == 0) { sa[0] = a + g_px[2 * i]; sa[1] = b + g_px[2 * i + 1]; }
    }
    __syncthreads();
    float d = g_dinv[i];
    float a0 = sa[0] * d;
    float a1 = sa[1] * d;
    float h = a0 * W1[t] + a1 * W1[HID + t] + b1[t];
    g_p[(size_t)i * HID + t] = fmaxf(h, 0.f) * d;
}

// ---- CSR gather: 1 warp per dst node, float4 lanes (2 LDG.128/lane/row),
//      pair-unrolled -> 4 LDG.128 in flight ----
__global__ void k_gather() {
    int w = (blockIdx.x * blockDim.x + threadIdx.x) >> 5;
    int l = threadIdx.x & 31;
    if (w >= N_NODES) return;
    int beg = g_rowptr[w], n = g_deg[w];
    const float4* pself = (const float4*)(g_p + (size_t)w * HID);
    float4 a0 = pself[l];        // self-loop init
    float4 a1 = pself[l + 32];
    int e = 0;
    for (; e + 2 <= n; e += 2) {
        int s0 = g_eidx[beg + e];
        int s1 = g_eidx[beg + e + 1];
        const float4* p0 = (const float4*)(g_p + (size_t)s0 * HID);
        const float4* p1 = (const float4*)(g_p + (size_t)s1 * HID);
        float4 v00 = __ldg(p0 + l);
        float4 v01 = __ldg(p0 + l + 32);
        float4 v10 = __ldg(p1 + l);
        float4 v11 = __ldg(p1 + l + 32);
        a0.x += v00.x + v10.x; a0.y += v00.y + v10.y;
        a0.z += v00.z + v10.z; a0.w += v00.w + v10.w;
        a1.x += v01.x + v11.x; a1.y += v01.y + v11.y;
        a1.z += v01.z + v11.z; a1.w += v01.w + v11.w;
    }
    if (e < n) {
        int s0 = g_eidx[beg + e];
        const float4* p0 = (const float4*)(g_p + (size_t)s0 * HID);
        float4 v00 = __ldg(p0 + l);
        float4 v01 = __ldg(p0 + l + 32);
        a0.x += v00.x; a0.y += v00.y; a0.z += v00.z; a0.w += v00.w;
        a1.x += v01.x; a1.y += v01.y; a1.z += v01.z; a1.w += v01.w;
    }
    float4* ad = (float4*)(g_agg + (size_t)w * HID);
    ad[l] = a0;
    ad[l + 32] = a1;
}

// ---- TF32 tensor-core GEMM: out = (dinv⊙agg)@W + bias ----
// Block 128x128, 8 warps (2 M x 4 N), warp tile 64x32 as 4x4 mma m16n8k8.
// WRITE_P: out = relu(h)*dinv into g_p; else h into g_h.
#define AS_STRIDE 36   // 32 + 4 pad -> A-frag banks = 4g+q  (conflict-free)
#define BS_STRIDE 136  // 128 + 8 pad -> B-frag banks = 8q+g (conflict-free)
template <bool WRITE_P>
__global__ void __launch_bounds__(256, 2) k_gemm(const float* __restrict__ W,
                                                 const float* __restrict__ bias) {
    __shared__ uint32_t As[128 * AS_STRIDE];  // [m][k] tf32, 18432 B
    __shared__ uint32_t Bs[32 * BS_STRIDE];   // [k][n] tf32, 17408 B
    int tid = threadIdx.x;
    int lane = tid & 31;
    int warp = tid >> 5;
    int warp_m = warp & 1;        // 0..1
    int warp_n = warp >> 1;       // 0..3
    int g = lane >> 2;            // 0..7
    int q = lane & 3;             // 0..3
    int rowBase = blockIdx.y * 128;
    int colBase = blockIdx.x * 128;

    float c[4][4][4];             // [mi][ni][reg]
#pragma unroll
    for (int mi = 0; mi < 4; mi++)
#pragma unroll
        for (int ni = 0; ni < 4; ni++)
#pragma unroll
            for (int r = 0; r < 4; r++) c[mi][ni][r] = 0.f;

    for (int k0 = 0; k0 < HID; k0 += 32) {
        // A tile: 128x32 floats -> tf32, [m][k] padded
        {
            int m0 = tid >> 3;          // 0..31
            int kq = (tid & 7) * 4;     // 0,4,..28
#pragma unroll
            for (int i = 0; i < 4; i++) {
                int m = m0 + i * 32;
                int gr = rowBase + m;
                float4 v = (gr < N_NODES)
                    ? *(const float4*)&g_agg[(size_t)gr * HID + k0 + kq]
                    : make_float4(0.f, 0.f, 0.f, 0.f);
                uint32_t* dst = &As[m * AS_STRIDE + kq];
                dst[0] = f2tf32(v.x); dst[1] = f2tf32(v.y);
                dst[2] = f2tf32(v.z); dst[3] = f2tf32(v.w);
            }
        }
        // B tile: 32 k x 128 n floats -> tf32, [k][n] padded
        {
            int kk = tid >> 3;          // 0..31
            int nq = (tid & 7) * 4;
#pragma unroll
            for (int i = 0; i < 4; i++) {
                int n = nq + i * 32;
                float4 v = *(const float4*)&W[(size_t)(k0 + kk) * HID + colBase + n];
                uint32_t* dst = &Bs[kk * BS_STRIDE + n];
                dst[0] = f2tf32(v.x); dst[1] = f2tf32(v.y);
                dst[2] = f2tf32(v.z); dst[3] = f2tf32(v.w);
            }
        }
        __syncthreads();

#pragma unroll
        for (int ks = 0; ks < 4; ks++) {   // 4 k-steps of 8
            int kb = ks * 8;
            uint32_t a[4][4], b[4][2];
#pragma unroll
            for (int mi = 0; mi < 4; mi++) {
                int m = warp_m * 64 + mi * 16;
                const uint32_t* ap = &As[(m + g) * AS_STRIDE + kb + q];
                a[mi][0] = ap[0];
                a[mi][1] = ap[8 * AS_STRIDE];
                a[mi][2] = ap[4];
                a[mi][3] = ap[8 * AS_STRIDE + 4];
            }
#pragma unroll
            for (int ni = 0; ni < 4; ni++) {
                int n = warp_n * 32 + ni * 8;
                const uint32_t* bp = &Bs[(kb + q) * BS_STRIDE + n + g];
                b[ni][0] = bp[0];
                b[ni][1] = bp[4 * BS_STRIDE];
            }
#pragma unroll
            for (int mi = 0; mi < 4; mi++)
#pragma unroll
                for (int ni = 0; ni < 4; ni++) {
                    asm volatile(
                        "mma.sync.aligned.m16n8k8.row.col.f32.tf32.tf32.f32 "
                        "{%0,%1,%2,%3}, {%4,%5,%6,%7}, {%8,%9}, {%0,%1,%2,%3};"
                        : "+f"(c[mi][ni][0]), "+f"(c[mi][ni][1]),
                          "+f"(c[mi][ni][2]), "+f"(c[mi][ni][3])
                        : "r"(a[mi][0]), "r"(a[mi][1]), "r"(a[mi][2]), "r"(a[mi][3]),
                          "r"(b[ni][0]), "r"(b[ni][1]));
                }
        }
        __syncthreads();
    }

    // epilogue: c[mi][ni] regs map to rows (m+g, m+g+8), cols (n+2q, n+2q+1)
#pragma unroll
    for (int mi = 0; mi < 4; mi++) {
#pragma unroll
        for (int half = 0; half < 2; half++) {
            int r = rowBase + warp_m * 64 + mi * 16 + g + half * 8;
            if (r >= N_NODES) continue;
            float d = g_dinv[r];
#pragma unroll
            for (int ni = 0; ni < 4; ni++) {
                int cc = colBase + warp_n * 32 + ni * 8 + 2 * q;
                float v0 = d * c[mi][ni][half * 2 + 0] + bias[cc];
                float v1 = d * c[mi][ni][half * 2 + 1] + bias[cc + 1];
                if (WRITE_P) {
                    v0 = fmaxf(v0, 0.f) * d;
                    v1 = fmaxf(v1, 0.f) * d;
                    *(float2*)&g_p[(size_t)r * HID + cc] = make_float2(v0, v1);
                } else {
                    *(float2*)&g_h[(size_t)r * HID + cc] = make_float2(v0, v1);
                }
            }
        }
    }
}

// ---- mean pool: block per graph, binary-search bounds (batch sorted),
//      row loop unrolled x4 for MLP ----
__global__ void k_pool(const int* __restrict__ batch) {
    int g = blockIdx.x;
    int j = threadIdx.x;  // 256
    int a = 0, b = N_NODES;
    while (a < b) { int m = (a + b) >> 1; if (batch[m] < g) a = m + 1; else b = m; }
    int lo = a;
    b = N_NODES;
    while (a < b) { int m = (a + b) >> 1; if (batch[m] < g + 1) a = m + 1; else b = m; }
    int hi = a;
    float s0 = 0.f, s1 = 0.f, s2 = 0.f, s3 = 0.f;
    int r = lo;
    for (; r + 4 <= hi; r += 4) {
        s0 += g_h[(size_t)(r + 0) * HID + j];
        s1 += g_h[(size_t)(r + 1) * HID + j];
        s2 += g_h[(size_t)(r + 2) * HID + j];
        s3 += g_h[(size_t)(r + 3) * HID + j];
    }
    for (; r < hi; r++) s0 += g_h[(size_t)r * HID + j];
    float acc = (s0 + s1) + (s2 + s3);
    g_pool[g * HID + j] = acc / fmaxf((float)(hi - lo), 1.f);
}

// ---- head: lin1+relu, lin2 ----
__global__ void k_head(const float* __restrict__ l1w, const float* __restrict__ l1b,
                       const float* __restrict__ l2w, const float* __restrict__ l2b,
                       float* __restrict__ out) {
    __shared__ float gv[HID];
    __shared__ float red[4];
    int g = blockIdx.x, t = threadIdx.x;  // 128 threads
    gv[t] = g_pool[g * HID + t];
    gv[t + 128] = g_pool[g * HID + t + 128];
    __syncthreads();
    float acc = l1b[t];
#pragma unroll 8
    for (int k = 0; k < HID; k++) acc += gv[k] * l1w[k * 128 + t];
    acc = fmaxf(acc, 0.f) * l2w[t];
#pragma unroll
    for (int o = 16; o; o >>= 1) acc += __shfl_down_sync(0xffffffffu, acc, o);
    if ((t & 31) == 0) red[t >> 5] = acc;
    __syncthreads();
    if (t == 0) out[g] = red[0] + red[1] + red[2] + red[3] + l2b[0];
}

extern "C" void kernel_launch(void* const* d_in, const int* in_sizes, int n_in,
                              void* d_out, int out_size) {
    const float* x     = (const float*)d_in[0];
    const int* ei      = (const int*)d_in[1];   // int32 (JAX x32 mode)
    const int* bat     = (const int*)d_in[2];   // int32
    const float* W1 = (const float*)d_in[3];
    const float* b1 = (const float*)d_in[4];
    const float* Wl[3] = {(const float*)d_in[5], (const float*)d_in[7], (const float*)d_in[9]};
    const float* bl[3] = {(const float*)d_in[6], (const float*)d_in[8], (const float*)d_in[10]};
    const float* l1w = (const float*)d_in[11];
    const float* l1b = (const float*)d_in[12];
    const float* l2w = (const float*)d_in[13];
    const float* l2b = (const float*)d_in[14];
    float* out = (float*)d_out;

    // degrees + norm + CSR (dst-major), parallel scan
    k_zero<<<(N_NODES + 255) / 256, 256>>>();
    k_count<<<(N_EDGES + 255) / 256, 256>>>(ei);
    k_rsqrt_px<<<(N_NODES + 255) / 256, 256>>>(x);
    k_blocksum<<<NBLK, 256>>>();
    k_scanb<<<1, 256>>>();
    k_scan3<<<NBLK, 256>>>();
    k_fill<<<(N_EDGES + 255) / 256, 256>>>(ei);

    // layer 1: fused 2-wide gather + 2->256 transform + relu*dinv prep
    k_layer1<<<N_NODES, 256>>>(W1, b1);

    // layers 2..4: CSR gather + tf32 tensor-core GEMM with fused epilogue
    dim3 ggrid(HID / 128, (N_NODES + 127) / 128);
    k_gather<<<(N_NODES * 32 + 255) / 256, 256>>>();
    k_gemm<true><<<ggrid, 256>>>(Wl[0], bl[0]);
    k_gather<<<(N_NODES * 32 + 255) / 256, 256>>>();
    k_gemm<true><<<ggrid, 256>>>(Wl[1], bl[1]);
    k_gather<<<(N_NODES * 32 + 255) / 256, 256>>>();
    k_gemm<false><<<ggrid, 256>>>(Wl[2], bl[2]);

    // mean pool (no atomics) + MLP head
    k_pool<<<NG, 256>>>(bat);
    k_head<<<NG, 128>>>(l1w, l1b, l2w, l2b, out);
}